// round 6
// baseline (speedup 1.0000x reference)
#include <cuda_runtime.h>
#include <cuda_fp16.h>
#include <cstdint>

#define NC 5
#define NU 6144
#define NV 6144
#define ND 64
#define NB 4096
#define CAPM 448   // merged per-node list capacity: mean 307, sigma 17.4 -> 8 sigma

// ---------------- scratch (static device globals; no runtime allocation) ----
__device__ __align__(16) __half g_msg_a[NC * NV * ND];   // fp16 messages [C,V,D]
__device__ __align__(16) __half g_msg_b[NC * NU * ND];   // fp16 messages [C,U,D]
__device__ __align__(16) float g_hu[NU * ND];
__device__ __align__(16) float g_hv[NV * ND];
__device__ __align__(16) float g_zu[NU * ND];
__device__ __align__(16) float g_zv[NV * ND];
__device__ __align__(16) float g_zug[NB * ND];
__device__ __align__(16) float g_zvg[NB * ND];
__device__ __align__(16) float g_tmp[NC * NB * ND];
__device__ int g_rowcnt[NU];
__device__ int g_colcnt[NV];
__device__ __align__(16) unsigned short g_rowlist[NU * CAPM];  // value = c*NV+v
__device__ __align__(16) unsigned short g_collist[NV * CAPM];  // value = c*NU+u

// ---------------- bit-cast helpers ------------------------------------------
__device__ __forceinline__ unsigned h2u(half2 h) {
    return *reinterpret_cast<unsigned*>(&h);
}
__device__ __forceinline__ half2 u2h(unsigned u) {
    return *reinterpret_cast<half2*>(&u);
}

// ---------------- zero the cursors ------------------------------------------
__global__ void k_zero(void) {
    int i = blockIdx.x * blockDim.x + threadIdx.x;
    if (i < NU) g_rowcnt[i] = 0;
    if (i < NV) g_colcnt[i] = 0;
}

// ---------------- build merged direct-offset lists in ONE adj scan ----------
__device__ __forceinline__ void build_handle(unsigned j) {
    unsigned c = j / (unsigned)(NU * NV);
    unsigned r = j - c * (unsigned)(NU * NV);
    unsigned uu = r / (unsigned)NV;
    unsigned vv = r - uu * (unsigned)NV;
    int s = atomicAdd(&g_rowcnt[uu], 1);
    if (s < CAPM) g_rowlist[uu * CAPM + s] = (unsigned short)(c * NV + vv);
    int t = atomicAdd(&g_colcnt[vv], 1);
    if (t < CAPM) g_collist[vv * CAPM + t] = (unsigned short)(c * NU + uu);
}

// one 256-bit chunk = 8 floats starting at element j
__device__ __forceinline__ void build_vec8(unsigned long long a, unsigned long long b,
                                           unsigned long long c, unsigned long long d,
                                           unsigned j) {
    if (a | b | c | d) {
        if (a) {
            if ((unsigned)a)        build_handle(j + 0u);
            if ((unsigned)(a >> 32)) build_handle(j + 1u);
        }
        if (b) {
            if ((unsigned)b)        build_handle(j + 2u);
            if ((unsigned)(b >> 32)) build_handle(j + 3u);
        }
        if (c) {
            if ((unsigned)c)        build_handle(j + 4u);
            if ((unsigned)(c >> 32)) build_handle(j + 5u);
        }
        if (d) {
            if ((unsigned)d)        build_handle(j + 6u);
            if ((unsigned)(d >> 32)) build_handle(j + 7u);
        }
    }
}

// 256-bit global loads (sm_100+): ld.global.nc.v4.b64 — halves LDG issue count
__device__ __forceinline__ void ldg256(const char* p, unsigned long long& a,
                                       unsigned long long& b, unsigned long long& c,
                                       unsigned long long& d) {
    asm("ld.global.nc.v4.b64 {%0, %1, %2, %3}, [%4];"
        : "=l"(a), "=l"(b), "=l"(c), "=l"(d) : "l"(p));
}

__global__ void k_build(const float* __restrict__ adj) {
    const char* base = (const char*)adj;
    const unsigned TOT8 = (unsigned)(NC * NU * NV) / 8u;   // 256-bit chunks
    unsigned T = gridDim.x * blockDim.x;
    unsigned tid = blockIdx.x * blockDim.x + threadIdx.x;
    unsigned i = tid;
    for (; i + 3u * T < TOT8; i += 4u * T) {
        unsigned long long a0, b0, c0, d0, a1, b1, c1, d1;
        unsigned long long a2, b2, c2, d2, a3, b3, c3, d3;
        ldg256(base + (size_t)i * 32u, a0, b0, c0, d0);
        ldg256(base + (size_t)(i + T) * 32u, a1, b1, c1, d1);
        ldg256(base + (size_t)(i + 2u * T) * 32u, a2, b2, c2, d2);
        ldg256(base + (size_t)(i + 3u * T) * 32u, a3, b3, c3, d3);
        build_vec8(a0, b0, c0, d0, i * 8u);
        build_vec8(a1, b1, c1, d1, (i + T) * 8u);
        build_vec8(a2, b2, c2, d2, (i + 2u * T) * 8u);
        build_vec8(a3, b3, c3, d3, (i + 3u * T) * 8u);
    }
    for (; i < TOT8; i += T) {
        unsigned long long a, b, c, d;
        ldg256(base + (size_t)i * 32u, a, b, c, d);
        build_vec8(a, b, c, d, i * 8u);
    }
}

// ---------------- per-class dense transform (dual-sided) --------------------
// out[c,n,e] = sum_d X[n,d] W[c,d,e]; half_out selects fp16 vs fp32 output.
__global__ void k_transform2(const float* __restrict__ X0, const float* __restrict__ W0,
                             void* __restrict__ out0,
                             const float* __restrict__ X1, const float* __restrict__ W1,
                             void* __restrict__ out1, int N, int half_out) {
    __shared__ __align__(16) float Xs[64 * 65];
    __shared__ __align__(16) float Ws[64 * 64];
    int tid = threadIdx.x;               // 256 threads
    int c = blockIdx.y;
    int n0 = blockIdx.x * 64;
    const float* X = (blockIdx.z == 0) ? X0 : X1;
    const float* W = (blockIdx.z == 0) ? W0 : W1;
    void* out = (blockIdx.z == 0) ? out0 : out1;

    const float4* X4 = (const float4*)(X + (size_t)n0 * ND);
    const float4* W4 = (const float4*)(W + (size_t)c * ND * ND);
#pragma unroll
    for (int r = 0; r < 4; r++) {
        int f = tid + r * 256;
        float4 xv = X4[f];
        int n = f >> 4, q = f & 15;
        Xs[n * 65 + 4 * q + 0] = xv.x;
        Xs[n * 65 + 4 * q + 1] = xv.y;
        Xs[n * 65 + 4 * q + 2] = xv.z;
        Xs[n * 65 + 4 * q + 3] = xv.w;
        ((float4*)Ws)[f] = W4[f];
    }
    __syncthreads();

    int te = tid & 15, tn = tid >> 4;
    float a00=0,a01=0,a02=0,a03=0, a10=0,a11=0,a12=0,a13=0;
    float a20=0,a21=0,a22=0,a23=0, a30=0,a31=0,a32=0,a33=0;
#pragma unroll 8
    for (int d = 0; d < 64; d++) {
        float4 w = *(const float4*)&Ws[d * 64 + te * 4];
        float x0 = Xs[(tn * 4 + 0) * 65 + d];
        float x1 = Xs[(tn * 4 + 1) * 65 + d];
        float x2 = Xs[(tn * 4 + 2) * 65 + d];
        float x3 = Xs[(tn * 4 + 3) * 65 + d];
        a00 += x0 * w.x; a01 += x0 * w.y; a02 += x0 * w.z; a03 += x0 * w.w;
        a10 += x1 * w.x; a11 += x1 * w.y; a12 += x1 * w.z; a13 += x1 * w.w;
        a20 += x2 * w.x; a21 += x2 * w.y; a22 += x2 * w.z; a23 += x2 * w.w;
        a30 += x3 * w.x; a31 += x3 * w.y; a32 += x3 * w.z; a33 += x3 * w.w;
    }
    size_t rb = (size_t)c * N + n0 + tn * 4;
    if (half_out) {
        __half* ob = (__half*)out + rb * ND + te * 4;
        *(uint2*)(ob + 0 * ND) = make_uint2(h2u(__floats2half2_rn(a00, a01)),
                                            h2u(__floats2half2_rn(a02, a03)));
        *(uint2*)(ob + 1 * ND) = make_uint2(h2u(__floats2half2_rn(a10, a11)),
                                            h2u(__floats2half2_rn(a12, a13)));
        *(uint2*)(ob + 2 * ND) = make_uint2(h2u(__floats2half2_rn(a20, a21)),
                                            h2u(__floats2half2_rn(a22, a23)));
        *(uint2*)(ob + 3 * ND) = make_uint2(h2u(__floats2half2_rn(a30, a31)),
                                            h2u(__floats2half2_rn(a32, a33)));
    } else {
        float* ob = (float*)out + rb * ND + te * 4;
        *(float4*)(ob + 0 * ND) = make_float4(a00, a01, a02, a03);
        *(float4*)(ob + 1 * ND) = make_float4(a10, a11, a12, a13);
        *(float4*)(ob + 2 * ND) = make_float4(a20, a21, a22, a23);
        *(float4*)(ob + 3 * ND) = make_float4(a30, a31, a32, a33);
    }
}

// ---------------- merged sparse aggregation over fp16 messages --------------
__device__ __forceinline__ void hacc(float4& a, uint2 p) {
    float2 lo = __half22float2(u2h(p.x));
    float2 hi = __half22float2(u2h(p.y));
    a.x += lo.x; a.y += lo.y; a.z += hi.x; a.w += hi.y;
}

__global__ void k_gather2(float* __restrict__ outA, const __half* __restrict__ msgA,
                          const float* __restrict__ biasA,
                          float* __restrict__ outB, const __half* __restrict__ msgB,
                          const float* __restrict__ biasB, int do_relu) {
    __shared__ __align__(16) unsigned short sidx[4][CAPM];
    int warp = threadIdx.x >> 5, lane = threadIdx.x & 31;
    int node = blockIdx.x * 4 + warp;
    bool sideA = node < NU;
    int u = sideA ? node : node - NU;
    const __half* msg = sideA ? msgA : msgB;
    const float* bias = sideA ? biasA : biasB;
    float* out = sideA ? outA : outB;
    const int* cnt = sideA ? g_rowcnt : g_colcnt;
    const unsigned short* lists = sideA ? g_rowlist : g_collist;

    int m = cnt[u];
    if (m > CAPM) m = CAPM;

    // stage this node's index list into smem (16B chunks)
    const uint4* lg = (const uint4*)(lists + (size_t)u * CAPM);
    uint4* ls = (uint4*)sidx[warp];
    for (int k = lane; k * 8 < m; k += 32) ls[k] = lg[k];
    __syncwarp();

    int hw = lane >> 4;       // which of the 2 edges per iteration
    int l4 = lane & 15;       // 4-col slot within the 64-col row
    float4 acc = make_float4(0.f, 0.f, 0.f, 0.f);
    if (hw == 0) {
#pragma unroll
        for (int c = 0; c < NC; c++) {
            float4 bv = ((const float4*)(bias + c * ND))[l4];
            acc.x += bv.x; acc.y += bv.y; acc.z += bv.z; acc.w += bv.w;
        }
    }

    const uint2* mg = (const uint2*)msg;   // 8B units; row = 16 units
    const unsigned short* si = sidx[warp];
    int mm = m & ~7;
    for (int b = 0; b < mm; b += 8) {      // 8 edges per body, 4 per lane
        unsigned o0 = si[b + 0 + hw];
        unsigned o1 = si[b + 2 + hw];
        unsigned o2 = si[b + 4 + hw];
        unsigned o3 = si[b + 6 + hw];
        uint2 p0 = mg[o0 * 16u + l4];
        uint2 p1 = mg[o1 * 16u + l4];
        uint2 p2 = mg[o2 * 16u + l4];
        uint2 p3 = mg[o3 * 16u + l4];
        hacc(acc, p0); hacc(acc, p1); hacc(acc, p2); hacc(acc, p3);
    }
    for (int b = mm; b < m; b += 2) {      // tail (<8 edges)
        int e = b + hw;
        if (e < m) {
            uint2 p = mg[(unsigned)si[e] * 16u + l4];
            hacc(acc, p);
        }
    }
    // fold the two half-warp partials together
    acc.x += __shfl_xor_sync(0xffffffffu, acc.x, 16);
    acc.y += __shfl_xor_sync(0xffffffffu, acc.y, 16);
    acc.z += __shfl_xor_sync(0xffffffffu, acc.z, 16);
    acc.w += __shfl_xor_sync(0xffffffffu, acc.w, 16);
    if (hw == 0) {
        if (do_relu) {
            acc.x = fmaxf(acc.x, 0.f); acc.y = fmaxf(acc.y, 0.f);
            acc.z = fmaxf(acc.z, 0.f); acc.w = fmaxf(acc.w, 0.f);
        }
        ((float4*)(out + (size_t)u * ND))[l4] = acc;
    }
}

// ---------------- gather decoder pair rows ----------------------------------
__global__ void k_pairs(const int* __restrict__ ui, const int* __restrict__ vi) {
    int b = blockIdx.x, e = threadIdx.x;
    g_zug[b * ND + e] = g_zu[(size_t)ui[b] * ND + e];
    g_zvg[b * ND + e] = g_zv[(size_t)vi[b] * ND + e];
}

// ---------------- final dot: logits[b,c] = sum_e tmp[c,b,e] * zv[b,e] -------
__global__ void k_dot(float* __restrict__ out) {
    int b = blockIdx.x, lane = threadIdx.x;   // 32 threads
    float za = g_zvg[b * ND + lane];
    float zb = g_zvg[b * ND + 32 + lane];
#pragma unroll
    for (int c = 0; c < NC; c++) {
        const float* t = &g_tmp[((size_t)c * NB + b) * ND];
        float p = t[lane] * za + t[lane + 32] * zb;
#pragma unroll
        for (int o = 16; o; o >>= 1) p += __shfl_xor_sync(0xffffffffu, p, o);
        if (lane == 0) out[b * NC + c] = p;
    }
}

// ---------------- launcher ---------------------------------------------------
extern "C" void kernel_launch(void* const* d_in, const int* in_sizes, int n_in,
                              void* d_out, int out_size) {
    const int*   ui    = (const int*)d_in[0];
    const int*   vi    = (const int*)d_in[1];
    const float* u_emb = (const float*)d_in[2];
    const float* v_emb = (const float*)d_in[3];
    const float* W1u   = (const float*)d_in[4];
    const float* b1u   = (const float*)d_in[5];
    const float* W1v   = (const float*)d_in[6];
    const float* b1v   = (const float*)d_in[7];
    const float* W2u   = (const float*)d_in[8];
    const float* b2u   = (const float*)d_in[9];
    const float* W2v   = (const float*)d_in[10];
    const float* b2v   = (const float*)d_in[11];
    const float* Q     = (const float*)d_in[12];
    const float* adj   = (const float*)d_in[13];
    float* out = (float*)d_out;

    __half *msg_a, *msg_b;
    float *hu, *hv, *zu, *zv, *zug, *tmp;
    cudaGetSymbolAddress((void**)&msg_a, g_msg_a);
    cudaGetSymbolAddress((void**)&msg_b, g_msg_b);
    cudaGetSymbolAddress((void**)&hu, g_hu);
    cudaGetSymbolAddress((void**)&hv, g_hv);
    cudaGetSymbolAddress((void**)&zu, g_zu);
    cudaGetSymbolAddress((void**)&zv, g_zv);
    cudaGetSymbolAddress((void**)&zug, g_zug);
    cudaGetSymbolAddress((void**)&tmp, g_tmp);

    // adjacency index build (single 755 MB scan, 256-bit loads)
    k_zero<<<48, 256>>>();
    k_build<<<1184, 256>>>(adj);

    // layer 1 (both sides fused per launch; fp16 messages)
    k_transform2<<<dim3(NV / 64, NC, 2), 256>>>(v_emb, W1v, msg_a, u_emb, W1u, msg_b, NV, 1);
    k_gather2<<<(NU + NV) / 4, 128>>>(hu, msg_a, b1v, hv, msg_b, b1u, 1);

    // layer 2
    k_transform2<<<dim3(NV / 64, NC, 2), 256>>>(hv, W2u, msg_a, hu, W2v, msg_b, NV, 1);
    k_gather2<<<(NU + NV) / 4, 128>>>(zu, msg_a, b2u, zv, msg_b, b2v, 0);

    // bilinear decoder (fp32 throughout)
    k_pairs<<<NB, 64>>>(ui, vi);
    k_transform2<<<dim3(NB / 64, NC, 1), 256>>>(zug, Q, tmp, zug, Q, tmp, NB, 0);
    k_dot<<<NB, 32>>>(out);
}

// round 7
// speedup vs baseline: 1.1247x; 1.1247x over previous
#include <cuda_runtime.h>
#include <cuda_fp16.h>
#include <cstdint>

#define NC 5
#define NU 6144
#define NV 6144
#define ND 64
#define NB 4096
#define CAPM 448   // merged per-node list capacity: mean 307, sigma 17.4 -> 8 sigma

// ---------------- scratch (static device globals; no runtime allocation) ----
__device__ __align__(16) __half g_msg_a[NC * NV * ND];   // fp16 messages [C,V,D]
__device__ __align__(16) __half g_msg_b[NC * NU * ND];   // fp16 messages [C,U,D]
__device__ __align__(16) float g_hu[NU * ND];
__device__ __align__(16) float g_hv[NV * ND];
__device__ __align__(16) float g_zu[NU * ND];
__device__ __align__(16) float g_zv[NV * ND];
__device__ __align__(16) float g_zug[NB * ND];
__device__ __align__(16) float g_zvg[NB * ND];
__device__ __align__(16) float g_tmp[NC * NB * ND];
__device__ int g_rowcnt[NU];
__device__ int g_colcnt[NV];
__device__ __align__(16) unsigned short g_rowlist[NU * CAPM];  // value = c*NV+v
__device__ __align__(16) unsigned short g_collist[NV * CAPM];  // value = c*NU+u

// ---------------- bit-cast helpers ------------------------------------------
__device__ __forceinline__ unsigned h2u(half2 h) {
    return *reinterpret_cast<unsigned*>(&h);
}
__device__ __forceinline__ half2 u2h(unsigned u) {
    return *reinterpret_cast<half2*>(&u);
}

// ---------------- zero the cursors ------------------------------------------
__global__ void k_zero(void) {
    int i = blockIdx.x * blockDim.x + threadIdx.x;
    if (i < NU) g_rowcnt[i] = 0;
    if (i < NV) g_colcnt[i] = 0;
}

// ---------------- warp-cooperative adjacency build --------------------------
// 256-bit global loads (sm_100+)
__device__ __forceinline__ void ldg256(const char* p, unsigned long long& a,
                                       unsigned long long& b, unsigned long long& c,
                                       unsigned long long& d) {
    asm("ld.global.nc.v4.b64 {%0, %1, %2, %3}, [%4];"
        : "=l"(a), "=l"(b), "=l"(c), "=l"(d) : "l"(p));
}

// position of the (n+1)-th set bit of w (branch-free binary search; n < popc(w))
__device__ __forceinline__ int nth_bit(unsigned w, int n) {
    int p = 0;
#pragma unroll
    for (int sh = 16; sh; sh >>= 1) {
        if (__popc(w & ((1u << (p + sh)) - 1u)) <= n) p += sh;
    }
    return p;
}

#define NTILE  737280u   // (NC*NU*NV)/256
#define TPC    147456u   // (NU*NV)/256 tiles per class

__global__ void k_build(const float* __restrict__ adj) {
    int lane = threadIdx.x & 31;
    unsigned warp = (blockIdx.x * blockDim.x + threadIdx.x) >> 5;
    unsigned nwarp = (gridDim.x * blockDim.x) >> 5;

    for (unsigned tile = warp; tile < NTILE; tile += nwarp) {
        const char* p = (const char*)adj + (size_t)tile * 1024u + (unsigned)lane * 32u;
        unsigned long long a, b, c, d;
        ldg256(p, a, b, c, d);

        unsigned msk = 0;
        msk |= ((unsigned)a         != 0u) ? 0x01u : 0u;
        msk |= ((unsigned)(a >> 32) != 0u) ? 0x02u : 0u;
        msk |= ((unsigned)b         != 0u) ? 0x04u : 0u;
        msk |= ((unsigned)(b >> 32) != 0u) ? 0x08u : 0u;
        msk |= ((unsigned)c         != 0u) ? 0x10u : 0u;
        msk |= ((unsigned)(c >> 32) != 0u) ? 0x20u : 0u;
        msk |= ((unsigned)d         != 0u) ? 0x40u : 0u;
        msk |= ((unsigned)(d >> 32) != 0u) ? 0x80u : 0u;

        unsigned bal0 = __ballot_sync(0xffffffffu, msk & 0x01u);
        unsigned bal1 = __ballot_sync(0xffffffffu, msk & 0x02u);
        unsigned bal2 = __ballot_sync(0xffffffffu, msk & 0x04u);
        unsigned bal3 = __ballot_sync(0xffffffffu, msk & 0x08u);
        unsigned bal4 = __ballot_sync(0xffffffffu, msk & 0x10u);
        unsigned bal5 = __ballot_sync(0xffffffffu, msk & 0x20u);
        unsigned bal6 = __ballot_sync(0xffffffffu, msk & 0x40u);
        unsigned bal7 = __ballot_sync(0xffffffffu, msk & 0x80u);
        int c0 = __popc(bal0), c1 = __popc(bal1), c2 = __popc(bal2), c3 = __popc(bal3);
        int c4 = __popc(bal4), c5 = __popc(bal5), c6 = __popc(bal6), c7 = __popc(bal7);
        int total = ((c0 + c1) + (c2 + c3)) + ((c4 + c5) + (c6 + c7));
        if (total == 0) continue;

        unsigned cls = tile / TPC;
        unsigned rbase = (tile - cls * TPC) * 256u;
        unsigned crow = cls * (unsigned)NV;
        unsigned ccol = cls * (unsigned)NU;

        for (int n = lane; n < total; n += 32) {
            // locate slot + word (fully predicated, no dynamic register indexing)
            int rem = n, slot = 0;
            unsigned w = 0;
            if (slot == 0) { if (rem >= c0) { rem -= c0; slot = 1; } else w = bal0; }
            if (slot == 1) { if (rem >= c1) { rem -= c1; slot = 2; } else w = bal1; }
            if (slot == 2) { if (rem >= c2) { rem -= c2; slot = 3; } else w = bal2; }
            if (slot == 3) { if (rem >= c3) { rem -= c3; slot = 4; } else w = bal3; }
            if (slot == 4) { if (rem >= c4) { rem -= c4; slot = 5; } else w = bal4; }
            if (slot == 5) { if (rem >= c5) { rem -= c5; slot = 6; } else w = bal5; }
            if (slot == 6) { if (rem >= c6) { rem -= c6; slot = 7; } else w = bal6; }
            if (slot == 7) { w = bal7; }
            int t = nth_bit(w, rem);

            unsigned r = rbase + (unsigned)t * 8u + (unsigned)slot;
            unsigned uu = r / (unsigned)NV;
            unsigned vv = r - uu * (unsigned)NV;
            int s = atomicAdd(&g_rowcnt[uu], 1);
            if (s < CAPM) g_rowlist[uu * CAPM + s] = (unsigned short)(crow + vv);
            int q = atomicAdd(&g_colcnt[vv], 1);
            if (q < CAPM) g_collist[vv * CAPM + q] = (unsigned short)(ccol + uu);
        }
    }
}

// ---------------- per-class dense transform (dual-sided) --------------------
// out[c,n,e] = sum_d X[n,d] W[c,d,e]; half_out selects fp16 vs fp32 output.
__global__ void k_transform2(const float* __restrict__ X0, const float* __restrict__ W0,
                             void* __restrict__ out0,
                             const float* __restrict__ X1, const float* __restrict__ W1,
                             void* __restrict__ out1, int N, int half_out) {
    __shared__ __align__(16) float Xs[64 * 65];
    __shared__ __align__(16) float Ws[64 * 64];
    int tid = threadIdx.x;               // 256 threads
    int c = blockIdx.y;
    int n0 = blockIdx.x * 64;
    const float* X = (blockIdx.z == 0) ? X0 : X1;
    const float* W = (blockIdx.z == 0) ? W0 : W1;
    void* out = (blockIdx.z == 0) ? out0 : out1;

    const float4* X4 = (const float4*)(X + (size_t)n0 * ND);
    const float4* W4 = (const float4*)(W + (size_t)c * ND * ND);
#pragma unroll
    for (int r = 0; r < 4; r++) {
        int f = tid + r * 256;
        float4 xv = X4[f];
        int n = f >> 4, q = f & 15;
        Xs[n * 65 + 4 * q + 0] = xv.x;
        Xs[n * 65 + 4 * q + 1] = xv.y;
        Xs[n * 65 + 4 * q + 2] = xv.z;
        Xs[n * 65 + 4 * q + 3] = xv.w;
        ((float4*)Ws)[f] = W4[f];
    }
    __syncthreads();

    int te = tid & 15, tn = tid >> 4;
    float a00=0,a01=0,a02=0,a03=0, a10=0,a11=0,a12=0,a13=0;
    float a20=0,a21=0,a22=0,a23=0, a30=0,a31=0,a32=0,a33=0;
#pragma unroll 8
    for (int d = 0; d < 64; d++) {
        float4 w = *(const float4*)&Ws[d * 64 + te * 4];
        float x0 = Xs[(tn * 4 + 0) * 65 + d];
        float x1 = Xs[(tn * 4 + 1) * 65 + d];
        float x2 = Xs[(tn * 4 + 2) * 65 + d];
        float x3 = Xs[(tn * 4 + 3) * 65 + d];
        a00 += x0 * w.x; a01 += x0 * w.y; a02 += x0 * w.z; a03 += x0 * w.w;
        a10 += x1 * w.x; a11 += x1 * w.y; a12 += x1 * w.z; a13 += x1 * w.w;
        a20 += x2 * w.x; a21 += x2 * w.y; a22 += x2 * w.z; a23 += x2 * w.w;
        a30 += x3 * w.x; a31 += x3 * w.y; a32 += x3 * w.z; a33 += x3 * w.w;
    }
    size_t rb = (size_t)c * N + n0 + tn * 4;
    if (half_out) {
        __half* ob = (__half*)out + rb * ND + te * 4;
        *(uint2*)(ob + 0 * ND) = make_uint2(h2u(__floats2half2_rn(a00, a01)),
                                            h2u(__floats2half2_rn(a02, a03)));
        *(uint2*)(ob + 1 * ND) = make_uint2(h2u(__floats2half2_rn(a10, a11)),
                                            h2u(__floats2half2_rn(a12, a13)));
        *(uint2*)(ob + 2 * ND) = make_uint2(h2u(__floats2half2_rn(a20, a21)),
                                            h2u(__floats2half2_rn(a22, a23)));
        *(uint2*)(ob + 3 * ND) = make_uint2(h2u(__floats2half2_rn(a30, a31)),
                                            h2u(__floats2half2_rn(a32, a33)));
    } else {
        float* ob = (float*)out + rb * ND + te * 4;
        *(float4*)(ob + 0 * ND) = make_float4(a00, a01, a02, a03);
        *(float4*)(ob + 1 * ND) = make_float4(a10, a11, a12, a13);
        *(float4*)(ob + 2 * ND) = make_float4(a20, a21, a22, a23);
        *(float4*)(ob + 3 * ND) = make_float4(a30, a31, a32, a33);
    }
}

// ---------------- merged sparse aggregation over fp16 messages --------------
__device__ __forceinline__ void hacc(float4& a, uint2 p) {
    float2 lo = __half22float2(u2h(p.x));
    float2 hi = __half22float2(u2h(p.y));
    a.x += lo.x; a.y += lo.y; a.z += hi.x; a.w += hi.y;
}

__global__ void k_gather2(float* __restrict__ outA, const __half* __restrict__ msgA,
                          const float* __restrict__ biasA,
                          float* __restrict__ outB, const __half* __restrict__ msgB,
                          const float* __restrict__ biasB, int do_relu) {
    __shared__ __align__(16) unsigned short sidx[4][CAPM];
    int warp = threadIdx.x >> 5, lane = threadIdx.x & 31;
    int node = blockIdx.x * 4 + warp;
    bool sideA = node < NU;
    int u = sideA ? node : node - NU;
    const __half* msg = sideA ? msgA : msgB;
    const float* bias = sideA ? biasA : biasB;
    float* out = sideA ? outA : outB;
    const int* cnt = sideA ? g_rowcnt : g_colcnt;
    const unsigned short* lists = sideA ? g_rowlist : g_collist;

    int m = cnt[u];
    if (m > CAPM) m = CAPM;

    // stage this node's index list into smem (16B chunks)
    const uint4* lg = (const uint4*)(lists + (size_t)u * CAPM);
    uint4* ls = (uint4*)sidx[warp];
    for (int k = lane; k * 8 < m; k += 32) ls[k] = lg[k];
    __syncwarp();

    int hw = lane >> 4;       // which of the 2 edges per iteration
    int l4 = lane & 15;       // 4-col slot within the 64-col row
    float4 acc = make_float4(0.f, 0.f, 0.f, 0.f);
    if (hw == 0) {
#pragma unroll
        for (int c = 0; c < NC; c++) {
            float4 bv = ((const float4*)(bias + c * ND))[l4];
            acc.x += bv.x; acc.y += bv.y; acc.z += bv.z; acc.w += bv.w;
        }
    }

    const uint2* mg = (const uint2*)msg;   // 8B units; row = 16 units
    const unsigned short* si = sidx[warp];
    int mm = m & ~7;
    for (int b = 0; b < mm; b += 8) {      // 8 edges per body, 4 per lane
        unsigned o0 = si[b + 0 + hw];
        unsigned o1 = si[b + 2 + hw];
        unsigned o2 = si[b + 4 + hw];
        unsigned o3 = si[b + 6 + hw];
        uint2 p0 = mg[o0 * 16u + l4];
        uint2 p1 = mg[o1 * 16u + l4];
        uint2 p2 = mg[o2 * 16u + l4];
        uint2 p3 = mg[o3 * 16u + l4];
        hacc(acc, p0); hacc(acc, p1); hacc(acc, p2); hacc(acc, p3);
    }
    for (int b = mm; b < m; b += 2) {      // tail (<8 edges)
        int e = b + hw;
        if (e < m) {
            uint2 p = mg[(unsigned)si[e] * 16u + l4];
            hacc(acc, p);
        }
    }
    // fold the two half-warp partials together
    acc.x += __shfl_xor_sync(0xffffffffu, acc.x, 16);
    acc.y += __shfl_xor_sync(0xffffffffu, acc.y, 16);
    acc.z += __shfl_xor_sync(0xffffffffu, acc.z, 16);
    acc.w += __shfl_xor_sync(0xffffffffu, acc.w, 16);
    if (hw == 0) {
        if (do_relu) {
            acc.x = fmaxf(acc.x, 0.f); acc.y = fmaxf(acc.y, 0.f);
            acc.z = fmaxf(acc.z, 0.f); acc.w = fmaxf(acc.w, 0.f);
        }
        ((float4*)(out + (size_t)u * ND))[l4] = acc;
    }
}

// ---------------- gather decoder pair rows ----------------------------------
__global__ void k_pairs(const int* __restrict__ ui, const int* __restrict__ vi) {
    int b = blockIdx.x, e = threadIdx.x;
    g_zug[b * ND + e] = g_zu[(size_t)ui[b] * ND + e];
    g_zvg[b * ND + e] = g_zv[(size_t)vi[b] * ND + e];
}

// ---------------- final dot: logits[b,c] = sum_e tmp[c,b,e] * zv[b,e] -------
__global__ void k_dot(float* __restrict__ out) {
    int b = blockIdx.x, lane = threadIdx.x;   // 32 threads
    float za = g_zvg[b * ND + lane];
    float zb = g_zvg[b * ND + 32 + lane];
#pragma unroll
    for (int c = 0; c < NC; c++) {
        const float* t = &g_tmp[((size_t)c * NB + b) * ND];
        float p = t[lane] * za + t[lane + 32] * zb;
#pragma unroll
        for (int o = 16; o; o >>= 1) p += __shfl_xor_sync(0xffffffffu, p, o);
        if (lane == 0) out[b * NC + c] = p;
    }
}

// ---------------- launcher ---------------------------------------------------
extern "C" void kernel_launch(void* const* d_in, const int* in_sizes, int n_in,
                              void* d_out, int out_size) {
    const int*   ui    = (const int*)d_in[0];
    const int*   vi    = (const int*)d_in[1];
    const float* u_emb = (const float*)d_in[2];
    const float* v_emb = (const float*)d_in[3];
    const float* W1u   = (const float*)d_in[4];
    const float* b1u   = (const float*)d_in[5];
    const float* W1v   = (const float*)d_in[6];
    const float* b1v   = (const float*)d_in[7];
    const float* W2u   = (const float*)d_in[8];
    const float* b2u   = (const float*)d_in[9];
    const float* W2v   = (const float*)d_in[10];
    const float* b2v   = (const float*)d_in[11];
    const float* Q     = (const float*)d_in[12];
    const float* adj   = (const float*)d_in[13];
    float* out = (float*)d_out;

    __half *msg_a, *msg_b;
    float *hu, *hv, *zu, *zv, *zug, *tmp;
    cudaGetSymbolAddress((void**)&msg_a, g_msg_a);
    cudaGetSymbolAddress((void**)&msg_b, g_msg_b);
    cudaGetSymbolAddress((void**)&hu, g_hu);
    cudaGetSymbolAddress((void**)&hv, g_hv);
    cudaGetSymbolAddress((void**)&zu, g_zu);
    cudaGetSymbolAddress((void**)&zv, g_zv);
    cudaGetSymbolAddress((void**)&zug, g_zug);
    cudaGetSymbolAddress((void**)&tmp, g_tmp);

    // adjacency index build (warp-cooperative single scan)
    k_zero<<<48, 256>>>();
    k_build<<<1184, 256>>>(adj);

    // layer 1 (both sides fused per launch; fp16 messages)
    k_transform2<<<dim3(NV / 64, NC, 2), 256>>>(v_emb, W1v, msg_a, u_emb, W1u, msg_b, NV, 1);
    k_gather2<<<(NU + NV) / 4, 128>>>(hu, msg_a, b1v, hv, msg_b, b1u, 1);

    // layer 2
    k_transform2<<<dim3(NV / 64, NC, 2), 256>>>(hv, W2u, msg_a, hu, W2v, msg_b, NV, 1);
    k_gather2<<<(NU + NV) / 4, 128>>>(zu, msg_a, b2u, zv, msg_b, b2v, 0);

    // bilinear decoder (fp32 throughout)
    k_pairs<<<NB, 64>>>(ui, vi);
    k_transform2<<<dim3(NB / 64, NC, 1), 256>>>(zug, Q, tmp, zug, Q, tmp, NB, 0);
    k_dot<<<NB, 32>>>(out);
}

// round 8
// speedup vs baseline: 1.2241x; 1.0884x over previous
#include <cuda_runtime.h>
#include <cuda_fp16.h>
#include <cstdint>

#define NC 5
#define NU 6144
#define NV 6144
#define ND 64
#define NB 4096
#define CAPM 448   // merged per-node list capacity: mean 307, sigma 17.4 -> 8 sigma

// ---------------- scratch (static device globals; no runtime allocation) ----
__device__ __align__(16) __half g_msg_a[NC * NV * ND];   // fp16 messages [C,V,D]
__device__ __align__(16) __half g_msg_b[NC * NU * ND];   // fp16 messages [C,U,D]
__device__ __align__(16) float g_hu[NU * ND];
__device__ __align__(16) float g_hv[NV * ND];
__device__ __align__(16) float g_zu[NU * ND];
__device__ __align__(16) float g_zv[NV * ND];
__device__ __align__(16) float g_zug[NB * ND];
__device__ __align__(16) float g_zvg[NB * ND];
__device__ __align__(16) float g_tmp[NC * NB * ND];
__device__ int g_rowcnt[NU];
__device__ int g_colcnt[NV];
__device__ __align__(16) unsigned short g_rowlist[NU * CAPM];  // value = c*NV+v
__device__ __align__(16) unsigned short g_collist[NV * CAPM];  // value = c*NU+u

// ---------------- bit-cast helpers ------------------------------------------
__device__ __forceinline__ unsigned h2u(half2 h) {
    return *reinterpret_cast<unsigned*>(&h);
}
__device__ __forceinline__ half2 u2h(unsigned u) {
    return *reinterpret_cast<half2*>(&u);
}

// ---------------- zero the cursors ------------------------------------------
__global__ void k_zero(void) {
    int i = blockIdx.x * blockDim.x + threadIdx.x;
    if (i < NU) g_rowcnt[i] = 0;
    if (i < NV) g_colcnt[i] = 0;
}

// ---------------- warp-cooperative adjacency build (pipelined) --------------
// 256-bit global loads (sm_100+)
__device__ __forceinline__ void ldg256(const char* p, unsigned long long& a,
                                       unsigned long long& b, unsigned long long& c,
                                       unsigned long long& d) {
    asm("ld.global.nc.v4.b64 {%0, %1, %2, %3}, [%4];"
        : "=l"(a), "=l"(b), "=l"(c), "=l"(d) : "l"(p));
}

// position of the (n+1)-th set bit of w (branch-free binary search; n < popc(w))
__device__ __forceinline__ int nth_bit(unsigned w, int n) {
    int p = 0;
#pragma unroll
    for (int sh = 16; sh; sh >>= 1) {
        if (__popc(w & ((1u << (p + sh)) - 1u)) <= n) p += sh;
    }
    return p;
}

#define NTILE  737280u   // (NC*NU*NV)/256
#define TPC    147456u   // (NU*NV)/256 tiles per class

__device__ __forceinline__ void process_tile(unsigned tile, unsigned long long a,
                                             unsigned long long b, unsigned long long c,
                                             unsigned long long d, int lane) {
    unsigned msk = 0;
    msk |= ((unsigned)a         != 0u) ? 0x01u : 0u;
    msk |= ((unsigned)(a >> 32) != 0u) ? 0x02u : 0u;
    msk |= ((unsigned)b         != 0u) ? 0x04u : 0u;
    msk |= ((unsigned)(b >> 32) != 0u) ? 0x08u : 0u;
    msk |= ((unsigned)c         != 0u) ? 0x10u : 0u;
    msk |= ((unsigned)(c >> 32) != 0u) ? 0x20u : 0u;
    msk |= ((unsigned)d         != 0u) ? 0x40u : 0u;
    msk |= ((unsigned)(d >> 32) != 0u) ? 0x80u : 0u;

    if (__ballot_sync(0xffffffffu, msk) == 0u) return;

    unsigned bal0 = __ballot_sync(0xffffffffu, msk & 0x01u);
    unsigned bal1 = __ballot_sync(0xffffffffu, msk & 0x02u);
    unsigned bal2 = __ballot_sync(0xffffffffu, msk & 0x04u);
    unsigned bal3 = __ballot_sync(0xffffffffu, msk & 0x08u);
    unsigned bal4 = __ballot_sync(0xffffffffu, msk & 0x10u);
    unsigned bal5 = __ballot_sync(0xffffffffu, msk & 0x20u);
    unsigned bal6 = __ballot_sync(0xffffffffu, msk & 0x40u);
    unsigned bal7 = __ballot_sync(0xffffffffu, msk & 0x80u);
    int c0 = __popc(bal0), c1 = __popc(bal1), c2 = __popc(bal2), c3 = __popc(bal3);
    int c4 = __popc(bal4), c5 = __popc(bal5), c6 = __popc(bal6), c7 = __popc(bal7);
    int total = ((c0 + c1) + (c2 + c3)) + ((c4 + c5) + (c6 + c7));

    unsigned cls = tile / TPC;
    unsigned rbase = (tile - cls * TPC) * 256u;
    unsigned crow = cls * (unsigned)NV;
    unsigned ccol = cls * (unsigned)NU;

    for (int n = lane; n < total; n += 32) {
        int rem = n, slot = 0;
        unsigned w = 0;
        if (slot == 0) { if (rem >= c0) { rem -= c0; slot = 1; } else w = bal0; }
        if (slot == 1) { if (rem >= c1) { rem -= c1; slot = 2; } else w = bal1; }
        if (slot == 2) { if (rem >= c2) { rem -= c2; slot = 3; } else w = bal2; }
        if (slot == 3) { if (rem >= c3) { rem -= c3; slot = 4; } else w = bal3; }
        if (slot == 4) { if (rem >= c4) { rem -= c4; slot = 5; } else w = bal4; }
        if (slot == 5) { if (rem >= c5) { rem -= c5; slot = 6; } else w = bal5; }
        if (slot == 6) { if (rem >= c6) { rem -= c6; slot = 7; } else w = bal6; }
        if (slot == 7) { w = bal7; }
        int t = nth_bit(w, rem);

        unsigned r = rbase + (unsigned)t * 8u + (unsigned)slot;
        unsigned uu = r / (unsigned)NV;
        unsigned vv = r - uu * (unsigned)NV;
        int s = atomicAdd(&g_rowcnt[uu], 1);
        if (s < CAPM) g_rowlist[uu * CAPM + s] = (unsigned short)(crow + vv);
        int q = atomicAdd(&g_colcnt[vv], 1);
        if (q < CAPM) g_collist[vv * CAPM + q] = (unsigned short)(ccol + uu);
    }
}

__global__ void k_build(const float* __restrict__ adj) {
    int lane = threadIdx.x & 31;
    unsigned warp = (blockIdx.x * blockDim.x + threadIdx.x) >> 5;
    unsigned nwarp = (gridDim.x * blockDim.x) >> 5;
    const char* base = (const char*)adj + (unsigned)lane * 32u;

    unsigned t0 = warp;
    if (t0 >= NTILE) return;

    // 3-deep register pipeline: two tiles in flight ahead of processing
    unsigned long long a0, b0, c0, d0, a1, b1, c1, d1;
    ldg256(base + (size_t)t0 * 1024u, a0, b0, c0, d0);
    unsigned t1 = t0 + nwarp;
    bool h1 = t1 < NTILE;
    if (h1) ldg256(base + (size_t)t1 * 1024u, a1, b1, c1, d1);

    while (true) {
        unsigned t2 = t0 + 2u * nwarp;
        unsigned long long a2, b2, c2, d2;
        bool h2 = t2 < NTILE;
        if (h2) ldg256(base + (size_t)t2 * 1024u, a2, b2, c2, d2);

        process_tile(t0, a0, b0, c0, d0, lane);

        if (!h1) break;
        t0 = t1; a0 = a1; b0 = b1; c0 = c1; d0 = d1;
        t1 = t2; a1 = a2; b1 = b2; c1 = c2; d1 = d2;
        h1 = h2;
    }
}

// ---------------- per-class dense transform (dual-sided) --------------------
// out[c,n,e] = sum_d X[n,d] W[c,d,e]; half_out selects fp16 vs fp32 output.
__global__ void k_transform2(const float* __restrict__ X0, const float* __restrict__ W0,
                             void* __restrict__ out0,
                             const float* __restrict__ X1, const float* __restrict__ W1,
                             void* __restrict__ out1, int N, int half_out) {
    __shared__ __align__(16) float Xs[64 * 65];
    __shared__ __align__(16) float Ws[64 * 64];
    int tid = threadIdx.x;               // 256 threads
    int c = blockIdx.y;
    int n0 = blockIdx.x * 64;
    const float* X = (blockIdx.z == 0) ? X0 : X1;
    const float* W = (blockIdx.z == 0) ? W0 : W1;
    void* out = (blockIdx.z == 0) ? out0 : out1;

    const float4* X4 = (const float4*)(X + (size_t)n0 * ND);
    const float4* W4 = (const float4*)(W + (size_t)c * ND * ND);
#pragma unroll
    for (int r = 0; r < 4; r++) {
        int f = tid + r * 256;
        float4 xv = X4[f];
        int n = f >> 4, q = f & 15;
        Xs[n * 65 + 4 * q + 0] = xv.x;
        Xs[n * 65 + 4 * q + 1] = xv.y;
        Xs[n * 65 + 4 * q + 2] = xv.z;
        Xs[n * 65 + 4 * q + 3] = xv.w;
        ((float4*)Ws)[f] = W4[f];
    }
    __syncthreads();

    int te = tid & 15, tn = tid >> 4;
    float a00=0,a01=0,a02=0,a03=0, a10=0,a11=0,a12=0,a13=0;
    float a20=0,a21=0,a22=0,a23=0, a30=0,a31=0,a32=0,a33=0;
#pragma unroll 8
    for (int d = 0; d < 64; d++) {
        float4 w = *(const float4*)&Ws[d * 64 + te * 4];
        float x0 = Xs[(tn * 4 + 0) * 65 + d];
        float x1 = Xs[(tn * 4 + 1) * 65 + d];
        float x2 = Xs[(tn * 4 + 2) * 65 + d];
        float x3 = Xs[(tn * 4 + 3) * 65 + d];
        a00 += x0 * w.x; a01 += x0 * w.y; a02 += x0 * w.z; a03 += x0 * w.w;
        a10 += x1 * w.x; a11 += x1 * w.y; a12 += x1 * w.z; a13 += x1 * w.w;
        a20 += x2 * w.x; a21 += x2 * w.y; a22 += x2 * w.z; a23 += x2 * w.w;
        a30 += x3 * w.x; a31 += x3 * w.y; a32 += x3 * w.z; a33 += x3 * w.w;
    }
    size_t rb = (size_t)c * N + n0 + tn * 4;
    if (half_out) {
        __half* ob = (__half*)out + rb * ND + te * 4;
        *(uint2*)(ob + 0 * ND) = make_uint2(h2u(__floats2half2_rn(a00, a01)),
                                            h2u(__floats2half2_rn(a02, a03)));
        *(uint2*)(ob + 1 * ND) = make_uint2(h2u(__floats2half2_rn(a10, a11)),
                                            h2u(__floats2half2_rn(a12, a13)));
        *(uint2*)(ob + 2 * ND) = make_uint2(h2u(__floats2half2_rn(a20, a21)),
                                            h2u(__floats2half2_rn(a22, a23)));
        *(uint2*)(ob + 3 * ND) = make_uint2(h2u(__floats2half2_rn(a30, a31)),
                                            h2u(__floats2half2_rn(a32, a33)));
    } else {
        float* ob = (float*)out + rb * ND + te * 4;
        *(float4*)(ob + 0 * ND) = make_float4(a00, a01, a02, a03);
        *(float4*)(ob + 1 * ND) = make_float4(a10, a11, a12, a13);
        *(float4*)(ob + 2 * ND) = make_float4(a20, a21, a22, a23);
        *(float4*)(ob + 3 * ND) = make_float4(a30, a31, a32, a33);
    }
}

// ---------------- merged sparse aggregation over fp16 messages --------------
__device__ __forceinline__ void hacc(float4& a, uint2 p) {
    float2 lo = __half22float2(u2h(p.x));
    float2 hi = __half22float2(u2h(p.y));
    a.x += lo.x; a.y += lo.y; a.z += hi.x; a.w += hi.y;
}

__global__ void k_gather2(float* __restrict__ outA, const __half* __restrict__ msgA,
                          const float* __restrict__ biasA,
                          float* __restrict__ outB, const __half* __restrict__ msgB,
                          const float* __restrict__ biasB, int do_relu) {
    __shared__ __align__(16) unsigned short sidx[4][CAPM];
    int warp = threadIdx.x >> 5, lane = threadIdx.x & 31;
    int node = blockIdx.x * 4 + warp;
    bool sideA = node < NU;
    int u = sideA ? node : node - NU;
    const __half* msg = sideA ? msgA : msgB;
    const float* bias = sideA ? biasA : biasB;
    float* out = sideA ? outA : outB;
    const int* cnt = sideA ? g_rowcnt : g_colcnt;
    const unsigned short* lists = sideA ? g_rowlist : g_collist;

    int m = cnt[u];
    if (m > CAPM) m = CAPM;

    // stage this node's index list into smem (16B chunks)
    const uint4* lg = (const uint4*)(lists + (size_t)u * CAPM);
    uint4* ls = (uint4*)sidx[warp];
    for (int k = lane; k * 8 < m; k += 32) ls[k] = lg[k];
    __syncwarp();

    int hw = lane >> 4;       // which of the 2 edges per iteration
    int l4 = lane & 15;       // 4-col slot within the 64-col row
    float4 acc = make_float4(0.f, 0.f, 0.f, 0.f);
    if (hw == 0) {
#pragma unroll
        for (int c = 0; c < NC; c++) {
            float4 bv = ((const float4*)(bias + c * ND))[l4];
            acc.x += bv.x; acc.y += bv.y; acc.z += bv.z; acc.w += bv.w;
        }
    }

    const uint2* mg = (const uint2*)msg;   // 8B units; row = 16 units
    const unsigned short* si = sidx[warp];
    int mm = m & ~7;
    for (int b = 0; b < mm; b += 8) {      // 8 edges per body, 4 per lane
        unsigned o0 = si[b + 0 + hw];
        unsigned o1 = si[b + 2 + hw];
        unsigned o2 = si[b + 4 + hw];
        unsigned o3 = si[b + 6 + hw];
        uint2 p0 = mg[o0 * 16u + l4];
        uint2 p1 = mg[o1 * 16u + l4];
        uint2 p2 = mg[o2 * 16u + l4];
        uint2 p3 = mg[o3 * 16u + l4];
        hacc(acc, p0); hacc(acc, p1); hacc(acc, p2); hacc(acc, p3);
    }
    for (int b = mm; b < m; b += 2) {      // tail (<8 edges)
        int e = b + hw;
        if (e < m) {
            uint2 p = mg[(unsigned)si[e] * 16u + l4];
            hacc(acc, p);
        }
    }
    // fold the two half-warp partials together
    acc.x += __shfl_xor_sync(0xffffffffu, acc.x, 16);
    acc.y += __shfl_xor_sync(0xffffffffu, acc.y, 16);
    acc.z += __shfl_xor_sync(0xffffffffu, acc.z, 16);
    acc.w += __shfl_xor_sync(0xffffffffu, acc.w, 16);
    if (hw == 0) {
        if (do_relu) {
            acc.x = fmaxf(acc.x, 0.f); acc.y = fmaxf(acc.y, 0.f);
            acc.z = fmaxf(acc.z, 0.f); acc.w = fmaxf(acc.w, 0.f);
        }
        ((float4*)(out + (size_t)u * ND))[l4] = acc;
    }
}

// ---------------- gather decoder pair rows ----------------------------------
__global__ void k_pairs(const int* __restrict__ ui, const int* __restrict__ vi) {
    int b = blockIdx.x, e = threadIdx.x;
    g_zug[b * ND + e] = g_zu[(size_t)ui[b] * ND + e];
    g_zvg[b * ND + e] = g_zv[(size_t)vi[b] * ND + e];
}

// ---------------- final dot: logits[b,c] = sum_e tmp[c,b,e] * zv[b,e] -------
__global__ void k_dot(float* __restrict__ out) {
    int b = blockIdx.x, lane = threadIdx.x;   // 32 threads
    float za = g_zvg[b * ND + lane];
    float zb = g_zvg[b * ND + 32 + lane];
#pragma unroll
    for (int c = 0; c < NC; c++) {
        const float* t = &g_tmp[((size_t)c * NB + b) * ND];
        float p = t[lane] * za + t[lane + 32] * zb;
#pragma unroll
        for (int o = 16; o; o >>= 1) p += __shfl_xor_sync(0xffffffffu, p, o);
        if (lane == 0) out[b * NC + c] = p;
    }
}

// ---------------- launcher ---------------------------------------------------
extern "C" void kernel_launch(void* const* d_in, const int* in_sizes, int n_in,
                              void* d_out, int out_size) {
    const int*   ui    = (const int*)d_in[0];
    const int*   vi    = (const int*)d_in[1];
    const float* u_emb = (const float*)d_in[2];
    const float* v_emb = (const float*)d_in[3];
    const float* W1u   = (const float*)d_in[4];
    const float* b1u   = (const float*)d_in[5];
    const float* W1v   = (const float*)d_in[6];
    const float* b1v   = (const float*)d_in[7];
    const float* W2u   = (const float*)d_in[8];
    const float* b2u   = (const float*)d_in[9];
    const float* W2v   = (const float*)d_in[10];
    const float* b2v   = (const float*)d_in[11];
    const float* Q     = (const float*)d_in[12];
    const float* adj   = (const float*)d_in[13];
    float* out = (float*)d_out;

    __half *msg_a, *msg_b;
    float *hu, *hv, *zu, *zv, *zug, *tmp;
    cudaGetSymbolAddress((void**)&msg_a, g_msg_a);
    cudaGetSymbolAddress((void**)&msg_b, g_msg_b);
    cudaGetSymbolAddress((void**)&hu, g_hu);
    cudaGetSymbolAddress((void**)&hv, g_hv);
    cudaGetSymbolAddress((void**)&zu, g_zu);
    cudaGetSymbolAddress((void**)&zv, g_zv);
    cudaGetSymbolAddress((void**)&zug, g_zug);
    cudaGetSymbolAddress((void**)&tmp, g_tmp);

    // adjacency index build (warp-cooperative, 3-deep pipelined scan)
    k_zero<<<48, 256>>>();
    k_build<<<1184, 256>>>(adj);

    // layer 1 (both sides fused per launch; fp16 messages)
    k_transform2<<<dim3(NV / 64, NC, 2), 256>>>(v_emb, W1v, msg_a, u_emb, W1u, msg_b, NV, 1);
    k_gather2<<<(NU + NV) / 4, 128>>>(hu, msg_a, b1v, hv, msg_b, b1u, 1);

    // layer 2
    k_transform2<<<dim3(NV / 64, NC, 2), 256>>>(hv, W2u, msg_a, hu, W2v, msg_b, NV, 1);
    k_gather2<<<(NU + NV) / 4, 128>>>(zu, msg_a, b2u, zv, msg_b, b2v, 0);

    // bilinear decoder (fp32 throughout)
    k_pairs<<<NB, 64>>>(ui, vi);
    k_transform2<<<dim3(NB / 64, NC, 1), 256>>>(zug, Q, tmp, zug, Q, tmp, NB, 0);
    k_dot<<<NB, 32>>>(out);
}

// round 9
// speedup vs baseline: 1.3193x; 1.0778x over previous
#include <cuda_runtime.h>
#include <cuda_fp16.h>
#include <cstdint>

#define NC 5
#define NU 6144
#define NV 6144
#define ND 64
#define NB 4096
#define CAPM 448   // merged per-node list capacity: mean 307, sigma 17.4 -> 8 sigma

// ---------------- scratch (static device globals; no runtime allocation) ----
__device__ __align__(16) __half g_msg_a[NC * NV * ND];   // fp16 messages [C,V,D]
__device__ __align__(16) __half g_msg_b[NC * NU * ND];   // fp16 messages [C,U,D]
__device__ __align__(16) float g_hu[NU * ND];
__device__ __align__(16) float g_hv[NV * ND];
__device__ __align__(16) float g_zu[NU * ND];
__device__ __align__(16) float g_zv[NV * ND];
__device__ __align__(16) float g_zug[NB * ND];
__device__ __align__(16) float g_zvg[NB * ND];
__device__ __align__(16) float g_tmp[NC * NB * ND];
__device__ int g_rowcnt[NU];
__device__ int g_colcnt[NV];
__device__ __align__(16) unsigned short g_rowlist[NU * CAPM];  // value = c*NV+v
__device__ __align__(16) unsigned short g_collist[NV * CAPM];  // value = c*NU+u

// ---------------- bit-cast helpers ------------------------------------------
__device__ __forceinline__ unsigned h2u(half2 h) {
    return *reinterpret_cast<unsigned*>(&h);
}
__device__ __forceinline__ half2 u2h(unsigned u) {
    return *reinterpret_cast<half2*>(&u);
}

// ---------------- zero the cursors ------------------------------------------
__global__ void k_zero(void) {
    int i = blockIdx.x * blockDim.x + threadIdx.x;
    if (i < NU) g_rowcnt[i] = 0;
    if (i < NV) g_colcnt[i] = 0;
}

// ---------------- adjacency build: per-lane extraction, no warp ops ---------
// A 256-element tile lies inside ONE adjacency row (NV = 24*256), so uu is
// constant per tile and vv = vbase + lane*8 + bit. Each lane handles its own
// 8 elements: popc -> one aggregated row atomic, ffs loop for the edges.
__device__ __forceinline__ void ldg256(const char* p, unsigned long long& a,
                                       unsigned long long& b, unsigned long long& c,
                                       unsigned long long& d) {
    asm("ld.global.nc.v4.b64 {%0, %1, %2, %3}, [%4];"
        : "=l"(a), "=l"(b), "=l"(c), "=l"(d) : "l"(p));
}

#define NTILE  737280u   // (NC*NU*NV)/256
#define TPC    147456u   // (NU*NV)/256 tiles per class
#define TPR    24u       // tiles per adjacency row (6144/256)

__device__ __forceinline__ void process_tile(unsigned tile, unsigned long long a,
                                             unsigned long long b, unsigned long long c,
                                             unsigned long long d, int lane) {
    unsigned msk = 0;
    msk |= ((unsigned)a         != 0u) ? 0x01u : 0u;
    msk |= ((unsigned)(a >> 32) != 0u) ? 0x02u : 0u;
    msk |= ((unsigned)b         != 0u) ? 0x04u : 0u;
    msk |= ((unsigned)(b >> 32) != 0u) ? 0x08u : 0u;
    msk |= ((unsigned)c         != 0u) ? 0x10u : 0u;
    msk |= ((unsigned)(c >> 32) != 0u) ? 0x20u : 0u;
    msk |= ((unsigned)d         != 0u) ? 0x40u : 0u;
    msk |= ((unsigned)(d >> 32) != 0u) ? 0x80u : 0u;

    if (msk) {
        unsigned cls = tile / TPC;
        unsigned rt  = tile - cls * TPC;          // tile within class
        unsigned uu  = rt / TPR;                  // constant row for the tile
        unsigned vb  = (rt - uu * TPR) * 256u + (unsigned)lane * 8u;
        unsigned crow = cls * (unsigned)NV;
        unsigned ccol = cls * (unsigned)NU;

        int cnt = __popc(msk);
        int s = atomicAdd(&g_rowcnt[uu], cnt);    // one aggregated row atomic/lane
        unsigned rl = uu * CAPM;
        while (msk) {
            int k = __ffs(msk) - 1;
            msk &= msk - 1u;
            unsigned vv = vb + (unsigned)k;
            if (s < CAPM) g_rowlist[rl + s] = (unsigned short)(crow + vv);
            s++;
            int q = atomicAdd(&g_colcnt[vv], 1);
            if (q < CAPM) g_collist[vv * CAPM + q] = (unsigned short)(ccol + uu);
        }
    }
}

__global__ void k_build(const float* __restrict__ adj) {
    int lane = threadIdx.x & 31;
    unsigned warp = (blockIdx.x * blockDim.x + threadIdx.x) >> 5;
    unsigned nwarp = (gridDim.x * blockDim.x) >> 5;
    const char* base = (const char*)adj + (unsigned)lane * 32u;

    unsigned t0 = warp;
    if (t0 >= NTILE) return;

    // 3-deep register pipeline: two tiles in flight ahead of processing
    unsigned long long a0, b0, c0, d0, a1, b1, c1, d1;
    ldg256(base + (size_t)t0 * 1024u, a0, b0, c0, d0);
    unsigned t1 = t0 + nwarp;
    bool h1 = t1 < NTILE;
    if (h1) ldg256(base + (size_t)t1 * 1024u, a1, b1, c1, d1);

    while (true) {
        unsigned t2 = t0 + 2u * nwarp;
        unsigned long long a2, b2, c2, d2;
        bool h2 = t2 < NTILE;
        if (h2) ldg256(base + (size_t)t2 * 1024u, a2, b2, c2, d2);

        process_tile(t0, a0, b0, c0, d0, lane);

        if (!h1) break;
        t0 = t1; a0 = a1; b0 = b1; c0 = c1; d0 = d1;
        t1 = t2; a1 = a2; b1 = b2; c1 = c2; d1 = d2;
        h1 = h2;
    }
}

// ---------------- per-class dense transform (dual-sided) --------------------
// out[c,n,e] = sum_d X[n,d] W[c,d,e]; half_out selects fp16 vs fp32 output.
__global__ void k_transform2(const float* __restrict__ X0, const float* __restrict__ W0,
                             void* __restrict__ out0,
                             const float* __restrict__ X1, const float* __restrict__ W1,
                             void* __restrict__ out1, int N, int half_out) {
    __shared__ __align__(16) float Xs[64 * 65];
    __shared__ __align__(16) float Ws[64 * 64];
    int tid = threadIdx.x;               // 256 threads
    int c = blockIdx.y;
    int n0 = blockIdx.x * 64;
    const float* X = (blockIdx.z == 0) ? X0 : X1;
    const float* W = (blockIdx.z == 0) ? W0 : W1;
    void* out = (blockIdx.z == 0) ? out0 : out1;

    const float4* X4 = (const float4*)(X + (size_t)n0 * ND);
    const float4* W4 = (const float4*)(W + (size_t)c * ND * ND);
#pragma unroll
    for (int r = 0; r < 4; r++) {
        int f = tid + r * 256;
        float4 xv = X4[f];
        int n = f >> 4, q = f & 15;
        Xs[n * 65 + 4 * q + 0] = xv.x;
        Xs[n * 65 + 4 * q + 1] = xv.y;
        Xs[n * 65 + 4 * q + 2] = xv.z;
        Xs[n * 65 + 4 * q + 3] = xv.w;
        ((float4*)Ws)[f] = W4[f];
    }
    __syncthreads();

    int te = tid & 15, tn = tid >> 4;
    float a00=0,a01=0,a02=0,a03=0, a10=0,a11=0,a12=0,a13=0;
    float a20=0,a21=0,a22=0,a23=0, a30=0,a31=0,a32=0,a33=0;
#pragma unroll 8
    for (int d = 0; d < 64; d++) {
        float4 w = *(const float4*)&Ws[d * 64 + te * 4];
        float x0 = Xs[(tn * 4 + 0) * 65 + d];
        float x1 = Xs[(tn * 4 + 1) * 65 + d];
        float x2 = Xs[(tn * 4 + 2) * 65 + d];
        float x3 = Xs[(tn * 4 + 3) * 65 + d];
        a00 += x0 * w.x; a01 += x0 * w.y; a02 += x0 * w.z; a03 += x0 * w.w;
        a10 += x1 * w.x; a11 += x1 * w.y; a12 += x1 * w.z; a13 += x1 * w.w;
        a20 += x2 * w.x; a21 += x2 * w.y; a22 += x2 * w.z; a23 += x2 * w.w;
        a30 += x3 * w.x; a31 += x3 * w.y; a32 += x3 * w.z; a33 += x3 * w.w;
    }
    size_t rb = (size_t)c * N + n0 + tn * 4;
    if (half_out) {
        __half* ob = (__half*)out + rb * ND + te * 4;
        *(uint2*)(ob + 0 * ND) = make_uint2(h2u(__floats2half2_rn(a00, a01)),
                                            h2u(__floats2half2_rn(a02, a03)));
        *(uint2*)(ob + 1 * ND) = make_uint2(h2u(__floats2half2_rn(a10, a11)),
                                            h2u(__floats2half2_rn(a12, a13)));
        *(uint2*)(ob + 2 * ND) = make_uint2(h2u(__floats2half2_rn(a20, a21)),
                                            h2u(__floats2half2_rn(a22, a23)));
        *(uint2*)(ob + 3 * ND) = make_uint2(h2u(__floats2half2_rn(a30, a31)),
                                            h2u(__floats2half2_rn(a32, a33)));
    } else {
        float* ob = (float*)out + rb * ND + te * 4;
        *(float4*)(ob + 0 * ND) = make_float4(a00, a01, a02, a03);
        *(float4*)(ob + 1 * ND) = make_float4(a10, a11, a12, a13);
        *(float4*)(ob + 2 * ND) = make_float4(a20, a21, a22, a23);
        *(float4*)(ob + 3 * ND) = make_float4(a30, a31, a32, a33);
    }
}

// ---------------- merged sparse aggregation over fp16 messages --------------
__device__ __forceinline__ void hacc(float4& a, uint2 p) {
    float2 lo = __half22float2(u2h(p.x));
    float2 hi = __half22float2(u2h(p.y));
    a.x += lo.x; a.y += lo.y; a.z += hi.x; a.w += hi.y;
}

__global__ void k_gather2(float* __restrict__ outA, const __half* __restrict__ msgA,
                          const float* __restrict__ biasA,
                          float* __restrict__ outB, const __half* __restrict__ msgB,
                          const float* __restrict__ biasB, int do_relu) {
    __shared__ __align__(16) unsigned short sidx[4][CAPM];
    int warp = threadIdx.x >> 5, lane = threadIdx.x & 31;
    int node = blockIdx.x * 4 + warp;
    bool sideA = node < NU;
    int u = sideA ? node : node - NU;
    const __half* msg = sideA ? msgA : msgB;
    const float* bias = sideA ? biasA : biasB;
    float* out = sideA ? outA : outB;
    const int* cnt = sideA ? g_rowcnt : g_colcnt;
    const unsigned short* lists = sideA ? g_rowlist : g_collist;

    int m = cnt[u];
    if (m > CAPM) m = CAPM;

    // stage this node's index list into smem (16B chunks)
    const uint4* lg = (const uint4*)(lists + (size_t)u * CAPM);
    uint4* ls = (uint4*)sidx[warp];
    for (int k = lane; k * 8 < m; k += 32) ls[k] = lg[k];
    __syncwarp();

    int hw = lane >> 4;       // which of the 2 edges per iteration
    int l4 = lane & 15;       // 4-col slot within the 64-col row
    float4 acc = make_float4(0.f, 0.f, 0.f, 0.f);
    if (hw == 0) {
#pragma unroll
        for (int c = 0; c < NC; c++) {
            float4 bv = ((const float4*)(bias + c * ND))[l4];
            acc.x += bv.x; acc.y += bv.y; acc.z += bv.z; acc.w += bv.w;
        }
    }

    const uint2* mg = (const uint2*)msg;   // 8B units; row = 16 units
    const unsigned short* si = sidx[warp];
    int mm = m & ~7;
    for (int b = 0; b < mm; b += 8) {      // 8 edges per body, 4 per lane
        unsigned o0 = si[b + 0 + hw];
        unsigned o1 = si[b + 2 + hw];
        unsigned o2 = si[b + 4 + hw];
        unsigned o3 = si[b + 6 + hw];
        uint2 p0 = mg[o0 * 16u + l4];
        uint2 p1 = mg[o1 * 16u + l4];
        uint2 p2 = mg[o2 * 16u + l4];
        uint2 p3 = mg[o3 * 16u + l4];
        hacc(acc, p0); hacc(acc, p1); hacc(acc, p2); hacc(acc, p3);
    }
    for (int b = mm; b < m; b += 2) {      // tail (<8 edges)
        int e = b + hw;
        if (e < m) {
            uint2 p = mg[(unsigned)si[e] * 16u + l4];
            hacc(acc, p);
        }
    }
    // fold the two half-warp partials together
    acc.x += __shfl_xor_sync(0xffffffffu, acc.x, 16);
    acc.y += __shfl_xor_sync(0xffffffffu, acc.y, 16);
    acc.z += __shfl_xor_sync(0xffffffffu, acc.z, 16);
    acc.w += __shfl_xor_sync(0xffffffffu, acc.w, 16);
    if (hw == 0) {
        if (do_relu) {
            acc.x = fmaxf(acc.x, 0.f); acc.y = fmaxf(acc.y, 0.f);
            acc.z = fmaxf(acc.z, 0.f); acc.w = fmaxf(acc.w, 0.f);
        }
        ((float4*)(out + (size_t)u * ND))[l4] = acc;
    }
}

// ---------------- gather decoder pair rows ----------------------------------
__global__ void k_pairs(const int* __restrict__ ui, const int* __restrict__ vi) {
    int b = blockIdx.x, e = threadIdx.x;
    g_zug[b * ND + e] = g_zu[(size_t)ui[b] * ND + e];
    g_zvg[b * ND + e] = g_zv[(size_t)vi[b] * ND + e];
}

// ---------------- final dot: logits[b,c] = sum_e tmp[c,b,e] * zv[b,e] -------
__global__ void k_dot(float* __restrict__ out) {
    int b = blockIdx.x, lane = threadIdx.x;   // 32 threads
    float za = g_zvg[b * ND + lane];
    float zb = g_zvg[b * ND + 32 + lane];
#pragma unroll
    for (int c = 0; c < NC; c++) {
        const float* t = &g_tmp[((size_t)c * NB + b) * ND];
        float p = t[lane] * za + t[lane + 32] * zb;
#pragma unroll
        for (int o = 16; o; o >>= 1) p += __shfl_xor_sync(0xffffffffu, p, o);
        if (lane == 0) out[b * NC + c] = p;
    }
}

// ---------------- launcher ---------------------------------------------------
extern "C" void kernel_launch(void* const* d_in, const int* in_sizes, int n_in,
                              void* d_out, int out_size) {
    const int*   ui    = (const int*)d_in[0];
    const int*   vi    = (const int*)d_in[1];
    const float* u_emb = (const float*)d_in[2];
    const float* v_emb = (const float*)d_in[3];
    const float* W1u   = (const float*)d_in[4];
    const float* b1u   = (const float*)d_in[5];
    const float* W1v   = (const float*)d_in[6];
    const float* b1v   = (const float*)d_in[7];
    const float* W2u   = (const float*)d_in[8];
    const float* b2u   = (const float*)d_in[9];
    const float* W2v   = (const float*)d_in[10];
    const float* b2v   = (const float*)d_in[11];
    const float* Q     = (const float*)d_in[12];
    const float* adj   = (const float*)d_in[13];
    float* out = (float*)d_out;

    __half *msg_a, *msg_b;
    float *hu, *hv, *zu, *zv, *zug, *tmp;
    cudaGetSymbolAddress((void**)&msg_a, g_msg_a);
    cudaGetSymbolAddress((void**)&msg_b, g_msg_b);
    cudaGetSymbolAddress((void**)&hu, g_hu);
    cudaGetSymbolAddress((void**)&hv, g_hv);
    cudaGetSymbolAddress((void**)&zu, g_zu);
    cudaGetSymbolAddress((void**)&zv, g_zv);
    cudaGetSymbolAddress((void**)&zug, g_zug);
    cudaGetSymbolAddress((void**)&tmp, g_tmp);

    // adjacency index build (per-lane extraction, 3-deep pipelined scan)
    k_zero<<<48, 256>>>();
    k_build<<<1184, 256>>>(adj);

    // layer 1 (both sides fused per launch; fp16 messages)
    k_transform2<<<dim3(NV / 64, NC, 2), 256>>>(v_emb, W1v, msg_a, u_emb, W1u, msg_b, NV, 1);
    k_gather2<<<(NU + NV) / 4, 128>>>(hu, msg_a, b1v, hv, msg_b, b1u, 1);

    // layer 2
    k_transform2<<<dim3(NV / 64, NC, 2), 256>>>(hv, W2u, msg_a, hu, W2v, msg_b, NV, 1);
    k_gather2<<<(NU + NV) / 4, 128>>>(zu, msg_a, b2u, zv, msg_b, b2v, 0);

    // bilinear decoder (fp32 throughout)
    k_pairs<<<NB, 64>>>(ui, vi);
    k_transform2<<<dim3(NB / 64, NC, 1), 256>>>(zug, Q, tmp, zug, Q, tmp, NB, 0);
    k_dot<<<NB, 32>>>(out);
}

// round 10
// speedup vs baseline: 1.3748x; 1.0421x over previous
#include <cuda_runtime.h>
#include <cuda_fp16.h>
#include <cstdint>

#define NC 5
#define NU 6144
#define NV 6144
#define ND 64
#define NB 4096
#define CAPM 448   // merged per-node list capacity: mean 307, sigma 17.4 -> 8 sigma

// ---------------- scratch (static device globals; no runtime allocation) ----
__device__ __align__(16) __half g_msg_a[NC * NV * ND];   // fp16 messages [C,V,D]
__device__ __align__(16) __half g_msg_b[NC * NU * ND];   // fp16 messages [C,U,D]
__device__ __align__(16) float g_hu[NU * ND];
__device__ __align__(16) float g_hv[NV * ND];
__device__ __align__(16) float g_zu[NU * ND];
__device__ __align__(16) float g_zv[NV * ND];
__device__ __align__(16) float g_tmp[NC * NB * ND];
__device__ int g_rowcnt[NU];
__device__ int g_colcnt[NV];
__device__ __align__(16) unsigned short g_rowlist[NU * CAPM];  // value = c*NV+v
__device__ __align__(16) unsigned short g_collist[NV * CAPM];  // value = c*NU+u

// ---------------- bit-cast helpers ------------------------------------------
__device__ __forceinline__ unsigned h2u(half2 h) {
    return *reinterpret_cast<unsigned*>(&h);
}
__device__ __forceinline__ half2 u2h(unsigned u) {
    return *reinterpret_cast<half2*>(&u);
}

// ---------------- zero the cursors ------------------------------------------
__global__ void k_zero(void) {
    int i = blockIdx.x * blockDim.x + threadIdx.x;
    if (i < NU) g_rowcnt[i] = 0;
    if (i < NV) g_colcnt[i] = 0;
}

// ---------------- adjacency build: per-lane extraction ----------------------
__device__ __forceinline__ void ldg256(const char* p, unsigned long long& a,
                                       unsigned long long& b, unsigned long long& c,
                                       unsigned long long& d) {
    asm("ld.global.nc.v4.b64 {%0, %1, %2, %3}, [%4];"
        : "=l"(a), "=l"(b), "=l"(c), "=l"(d) : "l"(p));
}

#define NTILE  737280u   // (NC*NU*NV)/256
#define TPC    147456u   // (NU*NV)/256 tiles per class
#define TPR    24u       // tiles per adjacency row (6144/256)

#define T1_BLKS    960u
#define BUILD_BLKS 1184u
#define FUSED_GRID (T1_BLKS + BUILD_BLKS)

__device__ __forceinline__ void process_tile(unsigned tile, unsigned long long a,
                                             unsigned long long b, unsigned long long c,
                                             unsigned long long d, int lane) {
    if ((a | b | c | d) == 0ull) return;   // fast path: 92% of lanes

    unsigned msk = 0;
    msk |= ((unsigned)a         != 0u) ? 0x01u : 0u;
    msk |= ((unsigned)(a >> 32) != 0u) ? 0x02u : 0u;
    msk |= ((unsigned)b         != 0u) ? 0x04u : 0u;
    msk |= ((unsigned)(b >> 32) != 0u) ? 0x08u : 0u;
    msk |= ((unsigned)c         != 0u) ? 0x10u : 0u;
    msk |= ((unsigned)(c >> 32) != 0u) ? 0x20u : 0u;
    msk |= ((unsigned)d         != 0u) ? 0x40u : 0u;
    msk |= ((unsigned)(d >> 32) != 0u) ? 0x80u : 0u;

    unsigned cls = tile / TPC;
    unsigned rt  = tile - cls * TPC;          // tile within class
    unsigned uu  = rt / TPR;                  // constant row for the tile
    unsigned vb  = (rt - uu * TPR) * 256u + (unsigned)lane * 8u;
    unsigned crow = cls * (unsigned)NV;
    unsigned ccol = cls * (unsigned)NU;

    int cnt = __popc(msk);
    int s = atomicAdd(&g_rowcnt[uu], cnt);    // one aggregated row atomic/lane
    unsigned rl = uu * CAPM;
    while (msk) {
        int k = __ffs(msk) - 1;
        msk &= msk - 1u;
        unsigned vv = vb + (unsigned)k;
        if (s < CAPM) g_rowlist[rl + s] = (unsigned short)(crow + vv);
        s++;
        int q = atomicAdd(&g_colcnt[vv], 1);
        if (q < CAPM) g_collist[vv * CAPM + q] = (unsigned short)(ccol + uu);
    }
}

// rotating 3-buffer pipeline: no register moves in steady state
__device__ void build_body(const float* __restrict__ adj, unsigned bbid) {
    int lane = threadIdx.x & 31;
    unsigned warp = (bbid * 256u + threadIdx.x) >> 5;
    const unsigned nwarp = (BUILD_BLKS * 256u) >> 5;   // 9472
    const char* base = (const char*)adj + (unsigned)lane * 32u;

    unsigned t = warp;
    unsigned long long aA, bA, cA, dA, aB, bB, cB, dB, aC, bC, cC, dC;
    ldg256(base + (size_t)t * 1024u, aA, bA, cA, dA);
    bool hB = (t + nwarp) < NTILE;
    if (hB) ldg256(base + (size_t)(t + nwarp) * 1024u, aB, bB, cB, dB);

    while (true) {
        bool hC = (t + 2u * nwarp) < NTILE;
        if (hC) ldg256(base + (size_t)(t + 2u * nwarp) * 1024u, aC, bC, cC, dC);
        process_tile(t, aA, bA, cA, dA, lane);
        if (!hB) return;
        t += nwarp;

        bool hA = (t + 2u * nwarp) < NTILE;
        if (hA) ldg256(base + (size_t)(t + 2u * nwarp) * 1024u, aA, bA, cA, dA);
        process_tile(t, aB, bB, cB, dB, lane);
        if (!hC) return;
        t += nwarp;

        hB = (t + 2u * nwarp) < NTILE;
        if (hB) ldg256(base + (size_t)(t + 2u * nwarp) * 1024u, aB, bB, cB, dB);
        process_tile(t, aC, bC, cC, dC, lane);
        if (!hA) return;
        t += nwarp;
    }
}

// ---------------- per-class dense transform body ----------------------------
// out[c,n,e] = sum_d X[n,d] W[c,d,e]; optional row gather via idx.
__device__ __forceinline__ void transform_body(
    int bx, int c, int z,
    const float* __restrict__ X0, const float* __restrict__ W0, void* __restrict__ out0,
    const float* __restrict__ X1, const float* __restrict__ W1, void* __restrict__ out1,
    int N, int half_out, const int* __restrict__ idx) {
    __shared__ __align__(16) float Xs[64 * 65];
    __shared__ __align__(16) float Ws[64 * 64];
    int tid = threadIdx.x;               // 256 threads
    int n0 = bx * 64;
    const float* X = (z == 0) ? X0 : X1;
    const float* W = (z == 0) ? W0 : W1;
    void* out = (z == 0) ? out0 : out1;

    const float4* X4 = (const float4*)(X + (size_t)n0 * ND);
    const float4* W4 = (const float4*)(W + (size_t)c * ND * ND);
#pragma unroll
    for (int r = 0; r < 4; r++) {
        int f = tid + r * 256;
        int n = f >> 4, q = f & 15;
        float4 xv;
        if (idx) {
            int row = idx[n0 + n];
            xv = ((const float4*)(X + (size_t)row * ND))[q];
        } else {
            xv = X4[f];
        }
        Xs[n * 65 + 4 * q + 0] = xv.x;
        Xs[n * 65 + 4 * q + 1] = xv.y;
        Xs[n * 65 + 4 * q + 2] = xv.z;
        Xs[n * 65 + 4 * q + 3] = xv.w;
        ((float4*)Ws)[f] = W4[f];
    }
    __syncthreads();

    int te = tid & 15, tn = tid >> 4;
    float a00=0,a01=0,a02=0,a03=0, a10=0,a11=0,a12=0,a13=0;
    float a20=0,a21=0,a22=0,a23=0, a30=0,a31=0,a32=0,a33=0;
#pragma unroll 8
    for (int d = 0; d < 64; d++) {
        float4 w = *(const float4*)&Ws[d * 64 + te * 4];
        float x0 = Xs[(tn * 4 + 0) * 65 + d];
        float x1 = Xs[(tn * 4 + 1) * 65 + d];
        float x2 = Xs[(tn * 4 + 2) * 65 + d];
        float x3 = Xs[(tn * 4 + 3) * 65 + d];
        a00 += x0 * w.x; a01 += x0 * w.y; a02 += x0 * w.z; a03 += x0 * w.w;
        a10 += x1 * w.x; a11 += x1 * w.y; a12 += x1 * w.z; a13 += x1 * w.w;
        a20 += x2 * w.x; a21 += x2 * w.y; a22 += x2 * w.z; a23 += x2 * w.w;
        a30 += x3 * w.x; a31 += x3 * w.y; a32 += x3 * w.z; a33 += x3 * w.w;
    }
    size_t rb = (size_t)c * N + n0 + tn * 4;
    if (half_out) {
        __half* ob = (__half*)out + rb * ND + te * 4;
        *(uint2*)(ob + 0 * ND) = make_uint2(h2u(__floats2half2_rn(a00, a01)),
                                            h2u(__floats2half2_rn(a02, a03)));
        *(uint2*)(ob + 1 * ND) = make_uint2(h2u(__floats2half2_rn(a10, a11)),
                                            h2u(__floats2half2_rn(a12, a13)));
        *(uint2*)(ob + 2 * ND) = make_uint2(h2u(__floats2half2_rn(a20, a21)),
                                            h2u(__floats2half2_rn(a22, a23)));
        *(uint2*)(ob + 3 * ND) = make_uint2(h2u(__floats2half2_rn(a30, a31)),
                                            h2u(__floats2half2_rn(a32, a33)));
    } else {
        float* ob = (float*)out + rb * ND + te * 4;
        *(float4*)(ob + 0 * ND) = make_float4(a00, a01, a02, a03);
        *(float4*)(ob + 1 * ND) = make_float4(a10, a11, a12, a13);
        *(float4*)(ob + 2 * ND) = make_float4(a20, a21, a22, a23);
        *(float4*)(ob + 3 * ND) = make_float4(a30, a31, a32, a33);
    }
}

// ---------------- fused: adjacency build + layer-1 transforms ---------------
// Interleaved roles: even bids < 1920 -> transform (960), rest -> build (1184),
// so every SM's first wave gets a mix and the short transforms hide inside the build.
__global__ void __launch_bounds__(256, 4)
k_fused1(const float* __restrict__ adj,
         const float* __restrict__ Xv, const float* __restrict__ W1v, __half* __restrict__ msg_a,
         const float* __restrict__ Xu, const float* __restrict__ W1u, __half* __restrict__ msg_b) {
    unsigned bid = blockIdx.x;
    bool is_t = (bid < 2u * T1_BLKS) && ((bid & 1u) == 0u);
    if (is_t) {
        unsigned tb = bid >> 1;                 // 0..959
        int bx = tb % 96;
        unsigned r = tb / 96;
        int c = r % NC, z = r / NC;
        transform_body(bx, c, z, Xv, W1v, msg_a, Xu, W1u, msg_b, NV, 1, nullptr);
    } else {
        unsigned bb = (bid < 2u * T1_BLKS) ? (bid >> 1) : (bid - T1_BLKS);
        build_body(adj, bb);
    }
}

// ---------------- standalone transform (layer 2 + decoder) ------------------
__global__ void k_transform2(const float* __restrict__ X0, const float* __restrict__ W0,
                             void* __restrict__ out0,
                             const float* __restrict__ X1, const float* __restrict__ W1,
                             void* __restrict__ out1, int N, int half_out,
                             const int* __restrict__ idx) {
    transform_body(blockIdx.x, blockIdx.y, blockIdx.z, X0, W0, out0, X1, W1, out1,
                   N, half_out, idx);
}

// ---------------- merged sparse aggregation over fp16 messages --------------
__device__ __forceinline__ void hacc(float4& a, uint2 p) {
    float2 lo = __half22float2(u2h(p.x));
    float2 hi = __half22float2(u2h(p.y));
    a.x += lo.x; a.y += lo.y; a.z += hi.x; a.w += hi.y;
}

__global__ void k_gather2(float* __restrict__ outA, const __half* __restrict__ msgA,
                          const float* __restrict__ biasA,
                          float* __restrict__ outB, const __half* __restrict__ msgB,
                          const float* __restrict__ biasB, int do_relu) {
    __shared__ __align__(16) unsigned short sidx[4][CAPM];
    int warp = threadIdx.x >> 5, lane = threadIdx.x & 31;
    int node = blockIdx.x * 4 + warp;
    bool sideA = node < NU;
    int u = sideA ? node : node - NU;
    const __half* msg = sideA ? msgA : msgB;
    const float* bias = sideA ? biasA : biasB;
    float* out = sideA ? outA : outB;
    const int* cnt = sideA ? g_rowcnt : g_colcnt;
    const unsigned short* lists = sideA ? g_rowlist : g_collist;

    int m = cnt[u];
    if (m > CAPM) m = CAPM;

    // stage this node's index list into smem (16B chunks)
    const uint4* lg = (const uint4*)(lists + (size_t)u * CAPM);
    uint4* ls = (uint4*)sidx[warp];
    for (int k = lane; k * 8 < m; k += 32) ls[k] = lg[k];
    __syncwarp();

    int hw = lane >> 4;       // which of the 2 edges per iteration
    int l4 = lane & 15;       // 4-col slot within the 64-col row
    float4 acc = make_float4(0.f, 0.f, 0.f, 0.f);
    if (hw == 0) {
#pragma unroll
        for (int c = 0; c < NC; c++) {
            float4 bv = ((const float4*)(bias + c * ND))[l4];
            acc.x += bv.x; acc.y += bv.y; acc.z += bv.z; acc.w += bv.w;
        }
    }

    const uint2* mg = (const uint2*)msg;   // 8B units; row = 16 units
    const unsigned short* si = sidx[warp];
    int mm = m & ~7;
    for (int b = 0; b < mm; b += 8) {      // 8 edges per body, 4 per lane
        unsigned o0 = si[b + 0 + hw];
        unsigned o1 = si[b + 2 + hw];
        unsigned o2 = si[b + 4 + hw];
        unsigned o3 = si[b + 6 + hw];
        uint2 p0 = mg[o0 * 16u + l4];
        uint2 p1 = mg[o1 * 16u + l4];
        uint2 p2 = mg[o2 * 16u + l4];
        uint2 p3 = mg[o3 * 16u + l4];
        hacc(acc, p0); hacc(acc, p1); hacc(acc, p2); hacc(acc, p3);
    }
    for (int b = mm; b < m; b += 2) {      // tail (<8 edges)
        int e = b + hw;
        if (e < m) {
            uint2 p = mg[(unsigned)si[e] * 16u + l4];
            hacc(acc, p);
        }
    }
    // fold the two half-warp partials together
    acc.x += __shfl_xor_sync(0xffffffffu, acc.x, 16);
    acc.y += __shfl_xor_sync(0xffffffffu, acc.y, 16);
    acc.z += __shfl_xor_sync(0xffffffffu, acc.z, 16);
    acc.w += __shfl_xor_sync(0xffffffffu, acc.w, 16);
    if (hw == 0) {
        if (do_relu) {
            acc.x = fmaxf(acc.x, 0.f); acc.y = fmaxf(acc.y, 0.f);
            acc.z = fmaxf(acc.z, 0.f); acc.w = fmaxf(acc.w, 0.f);
        }
        ((float4*)(out + (size_t)u * ND))[l4] = acc;
    }
}

// ---------------- final dot: logits[b,c] = sum_e tmp[c,b,e] * zv[vi[b],e] ---
__global__ void k_dot(const int* __restrict__ vi, float* __restrict__ out) {
    int b = blockIdx.x, lane = threadIdx.x;   // 32 threads
    int v = vi[b];
    float za = g_zv[(size_t)v * ND + lane];
    float zb = g_zv[(size_t)v * ND + 32 + lane];
#pragma unroll
    for (int c = 0; c < NC; c++) {
        const float* t = &g_tmp[((size_t)c * NB + b) * ND];
        float p = t[lane] * za + t[lane + 32] * zb;
#pragma unroll
        for (int o = 16; o; o >>= 1) p += __shfl_xor_sync(0xffffffffu, p, o);
        if (lane == 0) out[b * NC + c] = p;
    }
}

// ---------------- launcher ---------------------------------------------------
extern "C" void kernel_launch(void* const* d_in, const int* in_sizes, int n_in,
                              void* d_out, int out_size) {
    const int*   ui    = (const int*)d_in[0];
    const int*   vi    = (const int*)d_in[1];
    const float* u_emb = (const float*)d_in[2];
    const float* v_emb = (const float*)d_in[3];
    const float* W1u   = (const float*)d_in[4];
    const float* b1u   = (const float*)d_in[5];
    const float* W1v   = (const float*)d_in[6];
    const float* b1v   = (const float*)d_in[7];
    const float* W2u   = (const float*)d_in[8];
    const float* b2u   = (const float*)d_in[9];
    const float* W2v   = (const float*)d_in[10];
    const float* b2v   = (const float*)d_in[11];
    const float* Q     = (const float*)d_in[12];
    const float* adj   = (const float*)d_in[13];
    float* out = (float*)d_out;

    __half *msg_a, *msg_b;
    float *hu, *hv, *zu, *zv, *tmp;
    cudaGetSymbolAddress((void**)&msg_a, g_msg_a);
    cudaGetSymbolAddress((void**)&msg_b, g_msg_b);
    cudaGetSymbolAddress((void**)&hu, g_hu);
    cudaGetSymbolAddress((void**)&hv, g_hv);
    cudaGetSymbolAddress((void**)&zu, g_zu);
    cudaGetSymbolAddress((void**)&zv, g_zv);
    cudaGetSymbolAddress((void**)&tmp, g_tmp);

    // cursors, then fused build + layer-1 transforms (independent work overlapped)
    k_zero<<<48, 256>>>();
    k_fused1<<<FUSED_GRID, 256>>>(adj, v_emb, W1v, msg_a, u_emb, W1u, msg_b);

    // layer 1 gather
    k_gather2<<<(NU + NV) / 4, 128>>>(hu, msg_a, b1v, hv, msg_b, b1u, 1);

    // layer 2
    k_transform2<<<dim3(96, NC, 2), 256>>>(hv, W2u, msg_a, hu, W2v, msg_b, NV, 1, nullptr);
    k_gather2<<<(NU + NV) / 4, 128>>>(zu, msg_a, b2u, zv, msg_b, b2v, 0);

    // bilinear decoder: transform gathers zu rows via ui; dot gathers zv via vi
    k_transform2<<<dim3(NB / 64, NC, 1), 256>>>(zu, Q, tmp, zu, Q, tmp, NB, 0, ui);
    k_dot<<<NB, 32>>>(vi, out);
}